// round 1
// baseline (speedup 1.0000x reference)
#include <cuda_runtime.h>
#include <math.h>

// ---------------------------------------------------------------------------
// DMTet extraction, grid_res = 64 fixed.
//   vertices  : crossing grid edges, lexicographic (a,b) order
//               == (vertex id asc, direction code 1..7 asc)
//   faces     : 1-tri valid tets in tet order, then 2-tri tets (2 faces each)
// ---------------------------------------------------------------------------

#define GR   64
#define R1   65
#define R1SQ (R1 * R1)   // 4225

static constexpr int NVERT = R1 * R1 * R1;     // 274625
static constexpr int NCUBE = GR * GR * GR;     // 262144 = 2^18
static constexpr int NTET  = 6 * NCUBE;        // 1572864
static constexpr int EB    = (NVERT + 255) / 256;  // 1073 edge blocks
static constexpr int TB    = NTET / 256;           // 6144 tet blocks

// static scratch (no allocations allowed)
__device__ int g_edgeBS[EB];
__device__ int g_tetBS1[TB];
__device__ int g_tetBS2[TB];
__device__ int g_vertRank[NVERT * 7];
__device__ int g_Nv;
__device__ int g_N1;

// subset-chain paths for the 6 tets per cube: perms of adding bits (4,2,1)
__constant__ int c_path[6][4] = {
    {0,4,6,7},{0,4,5,7},{0,2,6,7},{0,2,3,7},{0,1,5,7},{0,1,3,7}};
__constant__ signed char c_numtri[16] = {0,1,1,2,1,2,2,1,1,2,2,1,2,1,1,0};
__constant__ signed char c_tritab[16][6] = {
    {-1,-1,-1,-1,-1,-1},
    { 1, 0, 2,-1,-1,-1},
    { 4, 0, 3,-1,-1,-1},
    { 1, 4, 2, 1, 3, 4},
    { 3, 1, 5,-1,-1,-1},
    { 2, 3, 0, 2, 5, 3},
    { 1, 4, 0, 1, 5, 4},
    { 4, 2, 5,-1,-1,-1},
    { 4, 5, 2,-1,-1,-1},
    { 4, 1, 0, 4, 5, 1},
    { 3, 2, 0, 3, 5, 2},
    { 1, 3, 5,-1,-1,-1},
    { 4, 1, 2, 4, 3, 1},
    { 3, 0, 4,-1,-1,-1},
    { 2, 0, 1,-1,-1,-1},
    {-1,-1,-1,-1,-1,-1}};
// BASE_TET_EDGES local vertex pairs
__constant__ signed char c_e1[6] = {0,0,0,1,1,2};
__constant__ signed char c_e2[6] = {1,2,3,2,3,3};

// ---------------------------------------------------------------------------
// helpers
// ---------------------------------------------------------------------------
__device__ __forceinline__ int corner_off(int m) {
    return (m >> 2) * R1SQ + ((m >> 1) & 1) * R1 + (m & 1);
}

// exclusive scan of one int per thread, 256 threads
__device__ __forceinline__ int block_excl_scan256(int val, int* wsum) {
    int lane = threadIdx.x & 31, w = threadIdx.x >> 5;
    int x = val;
    #pragma unroll
    for (int o = 1; o < 32; o <<= 1) {
        int y = __shfl_up_sync(0xffffffffu, x, o);
        if (lane >= o) x += y;
    }
    if (lane == 31) wsum[w] = x;
    __syncthreads();
    int off = 0;
    #pragma unroll
    for (int ww = 0; ww < 8; ww++) off += (ww < w) ? wsum[ww] : 0;
    return off + x - val;
}

// per-vertex crossing-edge mask (bit c set if edge (v, v + off(c)) crosses)
__device__ __forceinline__ int edge_mask(const float* __restrict__ sdf, int v,
                                         int i, int j, int k) {
    bool o = sdf[v] > 0.0f;
    int mask = 0;
    #pragma unroll
    for (int c = 1; c < 8; c++) {
        int di = c >> 2, dj = (c >> 1) & 1, dk = c & 1;
        if (i + di <= GR && j + dj <= GR && k + dk <= GR) {
            bool on = sdf[v + di * R1SQ + dj * R1 + dk] > 0.0f;
            if (o != on) mask |= (1 << c);
        }
    }
    return mask;
}

// ---------------------------------------------------------------------------
// pass 1a: per-block crossing-edge counts
// ---------------------------------------------------------------------------
__global__ void edge_count_kernel(const float* __restrict__ sdf) {
    __shared__ int wsum[8];
    int v = blockIdx.x * 256 + threadIdx.x;
    int cnt = 0;
    if (v < NVERT) {
        int k = v % R1; int t = v / R1; int j = t % R1; int i = t / R1;
        cnt = __popc(edge_mask(sdf, v, i, j, k));
    }
    int x = cnt;
    #pragma unroll
    for (int o = 16; o; o >>= 1) x += __shfl_down_sync(0xffffffffu, x, o);
    if ((threadIdx.x & 31) == 0) wsum[threadIdx.x >> 5] = x;
    __syncthreads();
    if (threadIdx.x == 0) {
        int s = 0;
        #pragma unroll
        for (int w = 0; w < 8; w++) s += wsum[w];
        g_edgeBS[blockIdx.x] = s;
    }
}

// ---------------------------------------------------------------------------
// pass 1b: per-block tet class counts (1-tri, 2-tri) packed 16/16
// ---------------------------------------------------------------------------
__device__ __forceinline__ int tet_index(const float* __restrict__ sdf,
                                         int perm, int base) {
    int idx = 0;
    #pragma unroll
    for (int l = 0; l < 4; l++) {
        int m = c_path[perm][l];
        idx |= (int)(sdf[base + corner_off(m)] > 0.0f) << l;
    }
    return idx;
}

__global__ void tet_count_kernel(const float* __restrict__ sdf) {
    __shared__ int wsum[8];
    int t = blockIdx.x * 256 + threadIdx.x;       // NTET multiple of 256
    int perm = t >> 18;
    int cube = t & (NCUBE - 1);
    int k = cube & 63, j = (cube >> 6) & 63, i = cube >> 12;
    int base = (i * R1 + j) * R1 + k;
    int nt = c_numtri[tet_index(sdf, perm, base)];
    int x = (nt == 1) + ((nt == 2) << 16);
    #pragma unroll
    for (int o = 16; o; o >>= 1) x += __shfl_down_sync(0xffffffffu, x, o);
    if ((threadIdx.x & 31) == 0) wsum[threadIdx.x >> 5] = x;
    __syncthreads();
    if (threadIdx.x == 0) {
        int s = 0;
        #pragma unroll
        for (int w = 0; w < 8; w++) s += wsum[w];
        g_tetBS1[blockIdx.x] = s & 0xffff;
        g_tetBS2[blockIdx.x] = s >> 16;
    }
}

// ---------------------------------------------------------------------------
// pass 2: in-place exclusive scan of the three partial arrays (3 blocks)
// ---------------------------------------------------------------------------
__device__ void scan_inplace(int* data, int n, int* totalDst) {
    __shared__ int warpS[32];
    int tid = threadIdx.x;
    int seg = (n + 1023) >> 10;           // <= 8 for our sizes
    int start = tid * seg;
    int end = min(start + seg, n);
    int vals[8];
    int s = 0;
    for (int idx = start, r = 0; idx < end; idx++, r++) {
        vals[r] = data[idx]; s += vals[r];
    }
    int lane = tid & 31, w = tid >> 5;
    int x = s;
    #pragma unroll
    for (int o = 1; o < 32; o <<= 1) {
        int y = __shfl_up_sync(0xffffffffu, x, o);
        if (lane >= o) x += y;
    }
    if (lane == 31) warpS[w] = x;
    __syncthreads();
    if (w == 0) {
        int v = warpS[lane];
        #pragma unroll
        for (int o = 1; o < 32; o <<= 1) {
            int y = __shfl_up_sync(0xffffffffu, v, o);
            if (lane >= o) v += y;
        }
        warpS[lane] = v;                   // inclusive scan of warp sums
    }
    __syncthreads();
    int warpOff = (w == 0) ? 0 : warpS[w - 1];
    int run = warpOff + x - s;             // exclusive prefix for this thread
    for (int idx = start, r = 0; idx < end; idx++, r++) {
        data[idx] = run; run += vals[r];
    }
    if (tid == 0 && totalDst) *totalDst = warpS[31];
}

__global__ void scan_kernel() {
    if (blockIdx.x == 0)      scan_inplace(g_edgeBS, EB, &g_Nv);
    else if (blockIdx.x == 1) scan_inplace(g_tetBS1, TB, &g_N1);
    else                      scan_inplace(g_tetBS2, TB, nullptr);
}

// ---------------------------------------------------------------------------
// pass 3: vertex features + vertRank
// ---------------------------------------------------------------------------
__device__ __forceinline__ float endpoint_vec(
    const float* __restrict__ feats, const float* __restrict__ sdf,
    const float* __restrict__ dir, const float* __restrict__ rot,
    const float* __restrict__ scl, int u, float e[6]) {
    float s  = tanhf(sdf[u]);
    float d0 = 0.0625f * tanhf(dir[2 * u]);
    float d1 = 0.0625f * tanhf(dir[2 * u + 1]);
    const float* m = rot + 9 * u;
    float m00 = m[0], m01 = m[1], m02 = m[2];
    float m10 = m[3], m11 = m[4], m12 = m[5];
    float m20 = m[6], m21 = m[7], m22 = m[8];
    float i00 = m11 * m22 - m12 * m21;
    float i01 = m02 * m21 - m01 * m22;
    float i02 = m01 * m12 - m02 * m11;
    float i10 = m12 * m20 - m10 * m22;
    float i11 = m00 * m22 - m02 * m20;
    float i12 = m02 * m10 - m00 * m12;
    float i20 = m10 * m21 - m11 * m20;
    float i21 = m01 * m20 - m00 * m21;
    float i22 = m00 * m11 - m01 * m10;
    float det = m00 * i00 + m01 * i10 + m02 * i20;
    float f   = scl[u] / det;
    e[0] = (i00 * d0 + i01 * d1 + i02) * f;
    e[1] = (i10 * d0 + i11 * d1 + i12) * f;
    e[2] = (i20 * d0 + i21 * d1 + i22) * f;
    e[3] = feats[6 * u + 3];
    e[4] = feats[6 * u + 4];
    e[5] = feats[6 * u + 5];
    return s;
}

__global__ void vert_kernel(const float* __restrict__ feats,
                            const float* __restrict__ sdf,
                            const float* __restrict__ dir,
                            const float* __restrict__ rot,
                            const float* __restrict__ scl,
                            float* __restrict__ out) {
    __shared__ int wsum[8];
    int v = blockIdx.x * 256 + threadIdx.x;
    int mask = 0;
    if (v < NVERT) {
        int k = v % R1; int t = v / R1; int j = t % R1; int i = t / R1;
        mask = edge_mask(sdf, v, i, j, k);
    }
    int cnt = __popc(mask);
    int excl = block_excl_scan256(cnt, wsum);
    if (cnt) {
        int rank = g_edgeBS[blockIdx.x] + excl;
        float ea[6];
        float sa = endpoint_vec(feats, sdf, dir, rot, scl, v, ea);
        #pragma unroll
        for (int c = 1; c < 8; c++) {
            if (mask & (1 << c)) {
                int u = v + (c >> 2) * R1SQ + ((c >> 1) & 1) * R1 + (c & 1);
                float eb[6];
                float sb = endpoint_vec(feats, sdf, dir, rot, scl, u, eb);
                float inv = 1.0f / (sa - sb);
                float wa = -sb * inv, wb = sa * inv;
                float* row = out + (long)rank * 6;
                #pragma unroll
                for (int q = 0; q < 6; q++) row[q] = ea[q] * wa + eb[q] * wb;
                g_vertRank[v * 7 + c - 1] = rank;
                rank++;
            }
        }
    }
}

// ---------------------------------------------------------------------------
// pass 4: faces
// ---------------------------------------------------------------------------
__global__ void face_kernel(const float* __restrict__ sdf,
                            float* __restrict__ out) {
    __shared__ int wsum[8];
    int t = blockIdx.x * 256 + threadIdx.x;
    int perm = t >> 18;
    int cube = t & (NCUBE - 1);
    int k = cube & 63, j = (cube >> 6) & 63, i = cube >> 12;
    int base = (i * R1 + j) * R1 + k;
    int idx = tet_index(sdf, perm, base);
    int nt = c_numtri[idx];
    int packed = (nt == 1) + ((nt == 2) << 16);
    int excl = block_excl_scan256(packed, wsum);
    if (nt) {
        int r1 = g_tetBS1[blockIdx.x] + (excl & 0xffff);
        int r2 = g_tetBS2[blockIdx.x] + (excl >> 16);
        long faceElemBase = (long)g_Nv * 6;
        int fi = (nt == 1) ? r1 : (g_N1 + 2 * r2);
        float* dst = out + faceElemBase + (long)fi * 3;
        int nent = nt * 3;
        for (int e = 0; e < nent; e++) {
            int le = c_tritab[idx][e];
            int l1 = c_e1[le], l2 = c_e2[le];
            int m  = c_path[perm][l1];
            int n  = c_path[perm][l2];
            int d  = m ^ n;                      // direction code 1..7
            int slot = (base + corner_off(m)) * 7 + d - 1;
            dst[e] = (float)g_vertRank[slot];
        }
    }
}

// ---------------------------------------------------------------------------
extern "C" void kernel_launch(void* const* d_in, const int* in_sizes, int n_in,
                              void* d_out, int out_size) {
    const float* feats = (const float*)d_in[0];  // (N,6)
    const float* sdf   = (const float*)d_in[1];  // (N,)
    const float* dir   = (const float*)d_in[2];  // (N,2)
    const float* rot   = (const float*)d_in[3];  // (N,3,3)
    const float* scl   = (const float*)d_in[4];  // (N,)
    float* out = (float*)d_out;
    (void)in_sizes; (void)n_in; (void)out_size;

    edge_count_kernel<<<EB, 256>>>(sdf);
    tet_count_kernel<<<TB, 256>>>(sdf);
    scan_kernel<<<3, 1024>>>();
    vert_kernel<<<EB, 256>>>(feats, sdf, dir, rot, scl, out);
    face_kernel<<<TB, 256>>>(sdf, out);
}

// round 2
// speedup vs baseline: 1.0733x; 1.0733x over previous
#include <cuda_runtime.h>
#include <math.h>

// ---------------------------------------------------------------------------
// DMTet extraction, grid_res = 64 fixed.
//   vertices  : crossing grid edges, lexicographic (a,b) order
//               == (vertex id asc, direction code 1..7 asc)
//   faces     : 1-tri valid tets in tet order, then 2-tri tets (2 faces each)
//
// R2: fused pass-1 (occ bitpack + edge mask byte + edge partials + per-vertex
// endpoint precompute); tet classification reads 34KB occ bits (L1-resident)
// instead of scattered sdf floats; vert pass is pure gather+lerp.
// ---------------------------------------------------------------------------

#define GR   64
#define R1   65
#define R1SQ (R1 * R1)   // 4225

static constexpr int NVERT = R1 * R1 * R1;         // 274625
static constexpr int NCUBE = GR * GR * GR;         // 262144
static constexpr int NTET  = 6 * NCUBE;            // 1572864
static constexpr int EB    = (NVERT + 255) / 256;  // 1073
static constexpr int TB    = NTET / 256;           // 6144
static constexpr int NOCCW = EB * 8;               // 8584 occ words

// static scratch (no allocations allowed)
__device__ int            g_edgeBS[EB];
__device__ int            g_tetBS1[TB];
__device__ int            g_tetBS2[TB];
__device__ int            g_vertRank[NVERT * 7];
__device__ unsigned int   g_occ[NOCCW];
__device__ unsigned char  g_mask[NVERT];
__device__ float4         g_ep[NVERT * 2];   // [e0..e3] [e4,e5,tanh(sdf),pad]
__device__ int            g_Nv;
__device__ int            g_N1;

// subset-chain paths for the 6 tets per cube: perms of adding bits (4,2,1)
__constant__ int c_path[6][4] = {
    {0,4,6,7},{0,4,5,7},{0,2,6,7},{0,2,3,7},{0,1,5,7},{0,1,3,7}};
__constant__ signed char c_numtri[16] = {0,1,1,2,1,2,2,1,1,2,2,1,2,1,1,0};
__constant__ signed char c_tritab[16][6] = {
    {-1,-1,-1,-1,-1,-1},
    { 1, 0, 2,-1,-1,-1},
    { 4, 0, 3,-1,-1,-1},
    { 1, 4, 2, 1, 3, 4},
    { 3, 1, 5,-1,-1,-1},
    { 2, 3, 0, 2, 5, 3},
    { 1, 4, 0, 1, 5, 4},
    { 4, 2, 5,-1,-1,-1},
    { 4, 5, 2,-1,-1,-1},
    { 4, 1, 0, 4, 5, 1},
    { 3, 2, 0, 3, 5, 2},
    { 1, 3, 5,-1,-1,-1},
    { 4, 1, 2, 4, 3, 1},
    { 3, 0, 4,-1,-1,-1},
    { 2, 0, 1,-1,-1,-1},
    {-1,-1,-1,-1,-1,-1}};
// BASE_TET_EDGES local vertex pairs
__constant__ signed char c_e1[6] = {0,0,0,1,1,2};
__constant__ signed char c_e2[6] = {1,2,3,2,3,3};

// ---------------------------------------------------------------------------
__device__ __forceinline__ int corner_off(int m) {
    return (m >> 2) * R1SQ + ((m >> 1) & 1) * R1 + (m & 1);
}

__device__ __forceinline__ int occ_bit(int vid) {
    return (g_occ[vid >> 5] >> (vid & 31)) & 1;
}

// exclusive scan of one int per thread, 256 threads
__device__ __forceinline__ int block_excl_scan256(int val, int* wsum) {
    int lane = threadIdx.x & 31, w = threadIdx.x >> 5;
    int x = val;
    #pragma unroll
    for (int o = 1; o < 32; o <<= 1) {
        int y = __shfl_up_sync(0xffffffffu, x, o);
        if (lane >= o) x += y;
    }
    if (lane == 31) wsum[w] = x;
    __syncthreads();
    int off = 0;
    #pragma unroll
    for (int ww = 0; ww < 8; ww++) off += (ww < w) ? wsum[ww] : 0;
    return off + x - val;
}

// ---------------------------------------------------------------------------
// pass 1: fused per-vertex pass
//   - occ bit pack
//   - crossing-edge mask (byte) + per-block edge count
//   - endpoint feature precompute -> g_ep
// ---------------------------------------------------------------------------
__global__ void __launch_bounds__(256) passA_kernel(
    const float* __restrict__ feats, const float* __restrict__ sdf,
    const float* __restrict__ dir,   const float* __restrict__ rot,
    const float* __restrict__ scl) {
    __shared__ int wsum[8];
    int v = blockIdx.x * 256 + threadIdx.x;
    bool inb = v < NVERT;
    float sv = inb ? sdf[v] : 0.0f;
    bool o = inb && (sv > 0.0f);

    unsigned ball = __ballot_sync(0xffffffffu, o);
    if ((threadIdx.x & 31) == 0) g_occ[(blockIdx.x << 3) + (threadIdx.x >> 5)] = ball;

    int mask = 0;
    if (inb) {
        int k = v % R1; int t = v / R1; int j = t % R1; int i = t / R1;
        #pragma unroll
        for (int c = 1; c < 8; c++) {
            int di = c >> 2, dj = (c >> 1) & 1, dk = c & 1;
            if (i + di <= GR && j + dj <= GR && k + dk <= GR) {
                bool on = sdf[v + di * R1SQ + dj * R1 + dk] > 0.0f;
                if (o != on) mask |= (1 << c);
            }
        }
        g_mask[v] = (unsigned char)mask;

        // endpoint precompute
        float s  = tanhf(sv);
        float d0 = 0.0625f * tanhf(dir[2 * v]);
        float d1 = 0.0625f * tanhf(dir[2 * v + 1]);
        const float* m = rot + 9 * v;
        float m00 = m[0], m01 = m[1], m02 = m[2];
        float m10 = m[3], m11 = m[4], m12 = m[5];
        float m20 = m[6], m21 = m[7], m22 = m[8];
        float i00 = m11 * m22 - m12 * m21;
        float i01 = m02 * m21 - m01 * m22;
        float i02 = m01 * m12 - m02 * m11;
        float i10 = m12 * m20 - m10 * m22;
        float i11 = m00 * m22 - m02 * m20;
        float i12 = m02 * m10 - m00 * m12;
        float i20 = m10 * m21 - m11 * m20;
        float i21 = m01 * m20 - m00 * m21;
        float i22 = m00 * m11 - m01 * m10;
        float det = m00 * i00 + m01 * i10 + m02 * i20;
        float f   = scl[v] / det;
        float4 a0, a1;
        a0.x = (i00 * d0 + i01 * d1 + i02) * f;
        a0.y = (i10 * d0 + i11 * d1 + i12) * f;
        a0.z = (i20 * d0 + i21 * d1 + i22) * f;
        a0.w = feats[6 * v + 3];
        a1.x = feats[6 * v + 4];
        a1.y = feats[6 * v + 5];
        a1.z = s;
        a1.w = 0.0f;
        g_ep[2 * v]     = a0;
        g_ep[2 * v + 1] = a1;
    }

    int x = __popc(mask);
    #pragma unroll
    for (int off = 16; off; off >>= 1) x += __shfl_down_sync(0xffffffffu, x, off);
    if ((threadIdx.x & 31) == 0) wsum[threadIdx.x >> 5] = x;
    __syncthreads();
    if (threadIdx.x == 0) {
        int s2 = 0;
        #pragma unroll
        for (int w = 0; w < 8; w++) s2 += wsum[w];
        g_edgeBS[blockIdx.x] = s2;
    }
}

// ---------------------------------------------------------------------------
// pass 1b: per-block tet class counts (occ bits, L1-resident 34KB)
// ---------------------------------------------------------------------------
__device__ __forceinline__ int tet_index_occ(int perm, int base) {
    int idx = 0;
    #pragma unroll
    for (int l = 0; l < 4; l++)
        idx |= occ_bit(base + corner_off(c_path[perm][l])) << l;
    return idx;
}

__global__ void __launch_bounds__(256) tet_count_kernel() {
    __shared__ int wsum[8];
    int t = blockIdx.x * 256 + threadIdx.x;
    int perm = t >> 18;
    int cube = t & (NCUBE - 1);
    int k = cube & 63, j = (cube >> 6) & 63, i = cube >> 12;
    int base = (i * R1 + j) * R1 + k;
    int nt = c_numtri[tet_index_occ(perm, base)];
    int x = (nt == 1) + ((nt == 2) << 16);
    #pragma unroll
    for (int o = 16; o; o >>= 1) x += __shfl_down_sync(0xffffffffu, x, o);
    if ((threadIdx.x & 31) == 0) wsum[threadIdx.x >> 5] = x;
    __syncthreads();
    if (threadIdx.x == 0) {
        int s = 0;
        #pragma unroll
        for (int w = 0; w < 8; w++) s += wsum[w];
        g_tetBS1[blockIdx.x] = s & 0xffff;
        g_tetBS2[blockIdx.x] = s >> 16;
    }
}

// ---------------------------------------------------------------------------
// pass 2: in-place exclusive scan of the three partial arrays (3 blocks)
// ---------------------------------------------------------------------------
__device__ void scan_inplace(int* data, int n, int* totalDst) {
    __shared__ int warpS[32];
    int tid = threadIdx.x;
    int seg = (n + 1023) >> 10;
    int start = tid * seg;
    int end = min(start + seg, n);
    int vals[8];
    int s = 0;
    for (int idx = start, r = 0; idx < end; idx++, r++) {
        vals[r] = data[idx]; s += vals[r];
    }
    int lane = tid & 31, w = tid >> 5;
    int x = s;
    #pragma unroll
    for (int o = 1; o < 32; o <<= 1) {
        int y = __shfl_up_sync(0xffffffffu, x, o);
        if (lane >= o) x += y;
    }
    if (lane == 31) warpS[w] = x;
    __syncthreads();
    if (w == 0) {
        int vv = warpS[lane];
        #pragma unroll
        for (int o = 1; o < 32; o <<= 1) {
            int y = __shfl_up_sync(0xffffffffu, vv, o);
            if (lane >= o) vv += y;
        }
        warpS[lane] = vv;
    }
    __syncthreads();
    int warpOff = (w == 0) ? 0 : warpS[w - 1];
    int run = warpOff + x - s;
    for (int idx = start, r = 0; idx < end; idx++, r++) {
        data[idx] = run; run += vals[r];
    }
    if (tid == 0 && totalDst) *totalDst = warpS[31];
}

__global__ void scan_kernel() {
    if (blockIdx.x == 0)      scan_inplace(g_edgeBS, EB, &g_Nv);
    else if (blockIdx.x == 1) scan_inplace(g_tetBS1, TB, &g_N1);
    else                      scan_inplace(g_tetBS2, TB, nullptr);
}

// ---------------------------------------------------------------------------
// pass 3: vertex features (pure gather + lerp) + vertRank
// ---------------------------------------------------------------------------
__global__ void __launch_bounds__(256) vert_kernel(float* __restrict__ out) {
    __shared__ int wsum[8];
    int v = blockIdx.x * 256 + threadIdx.x;
    int mask = (v < NVERT) ? (int)g_mask[v] : 0;
    int cnt = __popc(mask);
    int excl = block_excl_scan256(cnt, wsum);
    if (cnt) {
        int rank = g_edgeBS[blockIdx.x] + excl;
        float4 a0 = g_ep[2 * v];
        float4 a1 = g_ep[2 * v + 1];
        float sa = a1.z;
        #pragma unroll
        for (int c = 1; c < 8; c++) {
            if (mask & (1 << c)) {
                int u = v + (c >> 2) * R1SQ + ((c >> 1) & 1) * R1 + (c & 1);
                float4 b0 = g_ep[2 * u];
                float4 b1 = g_ep[2 * u + 1];
                float sb = b1.z;
                float inv = 1.0f / (sa - sb);
                float wa = -sb * inv, wb = sa * inv;
                float2* row = (float2*)(out + (long)rank * 6);
                float2 r0, r1, r2;
                r0.x = a0.x * wa + b0.x * wb;
                r0.y = a0.y * wa + b0.y * wb;
                r1.x = a0.z * wa + b0.z * wb;
                r1.y = a0.w * wa + b0.w * wb;
                r2.x = a1.x * wa + b1.x * wb;
                r2.y = a1.y * wa + b1.y * wb;
                row[0] = r0; row[1] = r1; row[2] = r2;
                g_vertRank[v * 7 + c - 1] = rank;
                rank++;
            }
        }
    }
}

// ---------------------------------------------------------------------------
// pass 4: faces
// ---------------------------------------------------------------------------
__global__ void __launch_bounds__(256) face_kernel(float* __restrict__ out) {
    __shared__ int wsum[8];
    int t = blockIdx.x * 256 + threadIdx.x;
    int perm = t >> 18;
    int cube = t & (NCUBE - 1);
    int k = cube & 63, j = (cube >> 6) & 63, i = cube >> 12;
    int base = (i * R1 + j) * R1 + k;
    int idx = tet_index_occ(perm, base);
    int nt = c_numtri[idx];
    int packed = (nt == 1) + ((nt == 2) << 16);
    int excl = block_excl_scan256(packed, wsum);
    if (nt) {
        int r1 = g_tetBS1[blockIdx.x] + (excl & 0xffff);
        int r2 = g_tetBS2[blockIdx.x] + (excl >> 16);
        long faceElemBase = (long)g_Nv * 6;
        int fi = (nt == 1) ? r1 : (g_N1 + 2 * r2);
        float* dst = out + faceElemBase + (long)fi * 3;
        int nent = nt * 3;
        for (int e = 0; e < nent; e++) {
            int le = c_tritab[idx][e];
            int l1 = c_e1[le], l2 = c_e2[le];
            int m  = c_path[perm][l1];
            int n  = c_path[perm][l2];
            int d  = m ^ n;
            int slot = (base + corner_off(m)) * 7 + d - 1;
            dst[e] = (float)g_vertRank[slot];
        }
    }
}

// ---------------------------------------------------------------------------
extern "C" void kernel_launch(void* const* d_in, const int* in_sizes, int n_in,
                              void* d_out, int out_size) {
    const float* feats = (const float*)d_in[0];  // (N,6)
    const float* sdf   = (const float*)d_in[1];  // (N,)
    const float* dir   = (const float*)d_in[2];  // (N,2)
    const float* rot   = (const float*)d_in[3];  // (N,3,3)
    const float* scl   = (const float*)d_in[4];  // (N,)
    float* out = (float*)d_out;
    (void)in_sizes; (void)n_in; (void)out_size;

    passA_kernel<<<EB, 256>>>(feats, sdf, dir, rot, scl);
    tet_count_kernel<<<TB, 256>>>();
    scan_kernel<<<3, 1024>>>();
    vert_kernel<<<EB, 256>>>(out);
    face_kernel<<<TB, 256>>>(out);
}

// round 8
// speedup vs baseline: 1.2001x; 1.1181x over previous
#include <cuda_runtime.h>
#include <math.h>

// ---------------------------------------------------------------------------
// DMTet extraction, grid_res = 64 fixed.
//   vertices  : crossing grid edges, lexicographic (a,b) order
//               == (vertex id asc, direction code 1..7 asc)
//   faces     : 1-tri valid tets in tet order, then 2-tri tets (2 faces each)
//
// R3 (resubmit x5 after infra timeouts): edge-per-thread vertex pass (MLP),
// packed rank+mask word per vertex (1.1MB gather table for faces),
// cube-per-thread tet classification.
// ---------------------------------------------------------------------------

#define GR   64
#define R1   65
#define R1SQ (R1 * R1)   // 4225

static constexpr int NVERT = R1 * R1 * R1;         // 274625
static constexpr int NCUBE = GR * GR * GR;         // 262144
static constexpr int NTET  = 6 * NCUBE;            // 1572864
static constexpr int EB    = (NVERT + 255) / 256;  // 1073
static constexpr int TB    = NTET / 256;           // 6144
static constexpr int CB    = NCUBE / 256;          // 1024 cube blocks
static constexpr int NOCCW = EB * 8;               // occ words
static constexpr int NEDGE = NVERT * 7;            // 1922375

// static scratch (no allocations allowed)
__device__ int            g_edgeBS[EB];
__device__ int            g_tetBS1[TB];
__device__ int            g_tetBS2[TB];
__device__ unsigned int   g_vb[NVERT];      // (rankBase<<7) | mask
__device__ unsigned int   g_occ[NOCCW];
__device__ unsigned char  g_mask[NVERT];
__device__ float4         g_ep[NVERT * 2];  // [e0..e3] [e4,e5,tanh(sdf),pad]
__device__ int            g_Nv;
__device__ int            g_N1;

// subset-chain paths for the 6 tets per cube: perms of adding bits (4,2,1)
__constant__ int c_path[6][4] = {
    {0,4,6,7},{0,4,5,7},{0,2,6,7},{0,2,3,7},{0,1,5,7},{0,1,3,7}};
__constant__ signed char c_numtri[16] = {0,1,1,2,1,2,2,1,1,2,2,1,2,1,1,0};
__constant__ signed char c_tritab[16][6] = {
    {-1,-1,-1,-1,-1,-1},
    { 1, 0, 2,-1,-1,-1},
    { 4, 0, 3,-1,-1,-1},
    { 1, 4, 2, 1, 3, 4},
    { 3, 1, 5,-1,-1,-1},
    { 2, 3, 0, 2, 5, 3},
    { 1, 4, 0, 1, 5, 4},
    { 4, 2, 5,-1,-1,-1},
    { 4, 5, 2,-1,-1,-1},
    { 4, 1, 0, 4, 5, 1},
    { 3, 2, 0, 3, 5, 2},
    { 1, 3, 5,-1,-1,-1},
    { 4, 1, 2, 4, 3, 1},
    { 3, 0, 4,-1,-1,-1},
    { 2, 0, 1,-1,-1,-1},
    {-1,-1,-1,-1,-1,-1}};
__constant__ signed char c_e1[6] = {0,0,0,1,1,2};
__constant__ signed char c_e2[6] = {1,2,3,2,3,3};

// ---------------------------------------------------------------------------
__device__ __forceinline__ int corner_off(int m) {
    return (m >> 2) * R1SQ + ((m >> 1) & 1) * R1 + (m & 1);
}
__device__ __forceinline__ int occ_bit(int vid) {
    return (g_occ[vid >> 5] >> (vid & 31)) & 1;
}
__device__ __forceinline__ int dir_off(int c) {
    return (c >> 2) * R1SQ + ((c >> 1) & 1) * R1 + (c & 1);
}

// exclusive scan of one int per thread, 256 threads
__device__ __forceinline__ int block_excl_scan256(int val, int* wsum) {
    int lane = threadIdx.x & 31, w = threadIdx.x >> 5;
    int x = val;
    #pragma unroll
    for (int o = 1; o < 32; o <<= 1) {
        int y = __shfl_up_sync(0xffffffffu, x, o);
        if (lane >= o) x += y;
    }
    if (lane == 31) wsum[w] = x;
    __syncthreads();
    int off = 0;
    #pragma unroll
    for (int ww = 0; ww < 8; ww++) off += (ww < w) ? wsum[ww] : 0;
    return off + x - val;
}

// ---------------------------------------------------------------------------
// pass 1: fused per-vertex pass: occ pack + mask + edge partials + endpoints
// ---------------------------------------------------------------------------
__global__ void __launch_bounds__(256) passA_kernel(
    const float* __restrict__ feats, const float* __restrict__ sdf,
    const float* __restrict__ dir,   const float* __restrict__ rot,
    const float* __restrict__ scl) {
    __shared__ int wsum[8];
    int v = blockIdx.x * 256 + threadIdx.x;
    bool inb = v < NVERT;
    float sv = inb ? sdf[v] : 0.0f;
    bool o = inb && (sv > 0.0f);

    unsigned ball = __ballot_sync(0xffffffffu, o);
    if ((threadIdx.x & 31) == 0) g_occ[(blockIdx.x << 3) + (threadIdx.x >> 5)] = ball;

    int mask = 0;
    if (inb) {
        int k = v % R1; int t = v / R1; int j = t % R1; int i = t / R1;
        #pragma unroll
        for (int c = 1; c < 8; c++) {
            int di = c >> 2, dj = (c >> 1) & 1, dk = c & 1;
            if (i + di <= GR && j + dj <= GR && k + dk <= GR) {
                bool on = sdf[v + di * R1SQ + dj * R1 + dk] > 0.0f;
                if (o != on) mask |= (1 << c);
            }
        }
        g_mask[v] = (unsigned char)mask;

        float s  = tanhf(sv);
        float d0 = 0.0625f * tanhf(dir[2 * v]);
        float d1 = 0.0625f * tanhf(dir[2 * v + 1]);
        const float* m = rot + 9 * v;
        float m00 = m[0], m01 = m[1], m02 = m[2];
        float m10 = m[3], m11 = m[4], m12 = m[5];
        float m20 = m[6], m21 = m[7], m22 = m[8];
        float i00 = m11 * m22 - m12 * m21;
        float i01 = m02 * m21 - m01 * m22;
        float i02 = m01 * m12 - m02 * m11;
        float i10 = m12 * m20 - m10 * m22;
        float i11 = m00 * m22 - m02 * m20;
        float i12 = m02 * m10 - m00 * m12;
        float i20 = m10 * m21 - m11 * m20;
        float i21 = m01 * m20 - m00 * m21;
        float i22 = m00 * m11 - m01 * m10;
        float det = m00 * i00 + m01 * i10 + m02 * i20;
        float f   = scl[v] / det;
        float4 a0, a1;
        a0.x = (i00 * d0 + i01 * d1 + i02) * f;
        a0.y = (i10 * d0 + i11 * d1 + i12) * f;
        a0.z = (i20 * d0 + i21 * d1 + i22) * f;
        a0.w = feats[6 * v + 3];
        a1.x = feats[6 * v + 4];
        a1.y = feats[6 * v + 5];
        a1.z = s;
        a1.w = 0.0f;
        g_ep[2 * v]     = a0;
        g_ep[2 * v + 1] = a1;
    }

    int x = __popc(mask);
    #pragma unroll
    for (int off = 16; off; off >>= 1) x += __shfl_down_sync(0xffffffffu, x, off);
    if ((threadIdx.x & 31) == 0) wsum[threadIdx.x >> 5] = x;
    __syncthreads();
    if (threadIdx.x == 0) {
        int s2 = 0;
        #pragma unroll
        for (int w = 0; w < 8; w++) s2 += wsum[w];
        g_edgeBS[blockIdx.x] = s2;
    }
}

// ---------------------------------------------------------------------------
// pass 1b: cube-per-thread tet class counts
//   tet id = perm*NCUBE + cube  ->  tet block = perm*CB + cubeBlock
// ---------------------------------------------------------------------------
__global__ void __launch_bounds__(256) tet_count_kernel() {
    __shared__ int wsum[8][6];
    int cube = blockIdx.x * 256 + threadIdx.x;
    int k = cube & 63, j = (cube >> 6) & 63, i = cube >> 12;
    int base = (i * R1 + j) * R1 + k;
    int cb = 0;   // 8 corner occ bits
    #pragma unroll
    for (int m = 0; m < 8; m++) cb |= occ_bit(base + corner_off(m)) << m;

    #pragma unroll
    for (int p = 0; p < 6; p++) {
        int idx = 0;
        #pragma unroll
        for (int l = 0; l < 4; l++) idx |= ((cb >> c_path[p][l]) & 1) << l;
        int nt = c_numtri[idx];
        int x = (nt == 1) + ((nt == 2) << 16);
        #pragma unroll
        for (int o = 16; o; o >>= 1) x += __shfl_down_sync(0xffffffffu, x, o);
        if ((threadIdx.x & 31) == 0) wsum[threadIdx.x >> 5][p] = x;
    }
    __syncthreads();
    if (threadIdx.x < 6) {
        int p = threadIdx.x;
        int s = 0;
        #pragma unroll
        for (int w = 0; w < 8; w++) s += wsum[w][p];
        g_tetBS1[p * CB + blockIdx.x] = s & 0xffff;
        g_tetBS2[p * CB + blockIdx.x] = s >> 16;
    }
}

// ---------------------------------------------------------------------------
// pass 2: in-place exclusive scans (3 blocks)
// ---------------------------------------------------------------------------
__device__ void scan_inplace(int* data, int n, int* totalDst) {
    __shared__ int warpS[32];
    int tid = threadIdx.x;
    int seg = (n + 1023) >> 10;
    int start = tid * seg;
    int end = min(start + seg, n);
    int vals[8];
    int s = 0;
    for (int idx = start, r = 0; idx < end; idx++, r++) {
        vals[r] = data[idx]; s += vals[r];
    }
    int lane = tid & 31, w = tid >> 5;
    int x = s;
    #pragma unroll
    for (int o = 1; o < 32; o <<= 1) {
        int y = __shfl_up_sync(0xffffffffu, x, o);
        if (lane >= o) x += y;
    }
    if (lane == 31) warpS[w] = x;
    __syncthreads();
    if (w == 0) {
        int vv = warpS[lane];
        #pragma unroll
        for (int o = 1; o < 32; o <<= 1) {
            int y = __shfl_up_sync(0xffffffffu, vv, o);
            if (lane >= o) vv += y;
        }
        warpS[lane] = vv;
    }
    __syncthreads();
    int warpOff = (w == 0) ? 0 : warpS[w - 1];
    int run = warpOff + x - s;
    for (int idx = start, r = 0; idx < end; idx++, r++) {
        data[idx] = run; run += vals[r];
    }
    if (tid == 0 && totalDst) *totalDst = warpS[31];
}

__global__ void scan_kernel() {
    if (blockIdx.x == 0)      scan_inplace(g_edgeBS, EB, &g_Nv);
    else if (blockIdx.x == 1) scan_inplace(g_tetBS1, TB, &g_N1);
    else                      scan_inplace(g_tetBS2, TB, nullptr);
}

// ---------------------------------------------------------------------------
// pass 2b: packed per-vertex word (rankBase<<7 | mask)
// ---------------------------------------------------------------------------
__global__ void __launch_bounds__(256) vbase_kernel() {
    __shared__ int wsum[8];
    int v = blockIdx.x * 256 + threadIdx.x;
    int mask = (v < NVERT) ? (int)g_mask[v] : 0;
    int cnt = __popc(mask);
    int excl = block_excl_scan256(cnt, wsum);
    if (v < NVERT) {
        unsigned base = (unsigned)(g_edgeBS[blockIdx.x] + excl);
        g_vb[v] = (base << 7) | (unsigned)(mask >> 1);  // bits 0..6 = dirs 1..7
    }
}

// ---------------------------------------------------------------------------
// pass 3: edge-per-thread vertex features
// ---------------------------------------------------------------------------
__global__ void __launch_bounds__(256) vert_kernel(float* __restrict__ out) {
    int eid = blockIdx.x * 256 + threadIdx.x;
    if (eid >= NEDGE) return;
    int v = eid / 7;
    int c = eid - v * 7 + 1;              // direction code 1..7
    unsigned word = g_vb[v];
    unsigned mb = word & 0x7fu;
    if (!((mb >> (c - 1)) & 1u)) return;
    int rank = (int)(word >> 7) + __popc(mb & ((1u << (c - 1)) - 1u));
    int u = v + dir_off(c);
    float4 a0 = g_ep[2 * v];
    float4 a1 = g_ep[2 * v + 1];
    float4 b0 = g_ep[2 * u];
    float4 b1 = g_ep[2 * u + 1];
    float sa = a1.z, sb = b1.z;
    float inv = 1.0f / (sa - sb);
    float wa = -sb * inv, wb = sa * inv;
    float2* row = (float2*)(out + (long)rank * 6);
    float2 r0, r1, r2;
    r0.x = a0.x * wa + b0.x * wb;
    r0.y = a0.y * wa + b0.y * wb;
    r1.x = a0.z * wa + b0.z * wb;
    r1.y = a0.w * wa + b0.w * wb;
    r2.x = a1.x * wa + b1.x * wb;
    r2.y = a1.y * wa + b1.y * wb;
    row[0] = r0; row[1] = r1; row[2] = r2;
}

// ---------------------------------------------------------------------------
// pass 4: faces (tet-per-thread, packed-word lookups)
// ---------------------------------------------------------------------------
__global__ void __launch_bounds__(256) face_kernel(float* __restrict__ out) {
    __shared__ int wsum[8];
    int t = blockIdx.x * 256 + threadIdx.x;
    int perm = t >> 18;
    int cube = t & (NCUBE - 1);
    int k = cube & 63, j = (cube >> 6) & 63, i = cube >> 12;
    int base = (i * R1 + j) * R1 + k;
    int idx = 0;
    #pragma unroll
    for (int l = 0; l < 4; l++)
        idx |= occ_bit(base + corner_off(c_path[perm][l])) << l;
    int nt = c_numtri[idx];
    int packed = (nt == 1) + ((nt == 2) << 16);
    int excl = block_excl_scan256(packed, wsum);
    if (nt) {
        int r1 = g_tetBS1[blockIdx.x] + (excl & 0xffff);
        int r2 = g_tetBS2[blockIdx.x] + (excl >> 16);
        long faceElemBase = (long)g_Nv * 6;
        int fi = (nt == 1) ? r1 : (g_N1 + 2 * r2);
        float* dst = out + faceElemBase + (long)fi * 3;
        int nent = nt * 3;
        for (int e = 0; e < nent; e++) {
            int le = c_tritab[idx][e];
            int l1 = c_e1[le], l2 = c_e2[le];
            int m  = c_path[perm][l1];
            int n  = c_path[perm][l2];
            int d  = m ^ n;                       // direction code 1..7
            unsigned word = g_vb[base + corner_off(m)];
            int rank = (int)(word >> 7) +
                       __popc((word & 0x7fu) & ((1u << (d - 1)) - 1u));
            dst[e] = (float)rank;
        }
    }
}

// ---------------------------------------------------------------------------
extern "C" void kernel_launch(void* const* d_in, const int* in_sizes, int n_in,
                              void* d_out, int out_size) {
    const float* feats = (const float*)d_in[0];  // (N,6)
    const float* sdf   = (const float*)d_in[1];  // (N,)
    const float* dir   = (const float*)d_in[2];  // (N,2)
    const float* rot   = (const float*)d_in[3];  // (N,3,3)
    const float* scl   = (const float*)d_in[4];  // (N,)
    float* out = (float*)d_out;
    (void)in_sizes; (void)n_in; (void)out_size;

    passA_kernel<<<EB, 256>>>(feats, sdf, dir, rot, scl);
    tet_count_kernel<<<CB, 256>>>();
    scan_kernel<<<3, 1024>>>();
    vbase_kernel<<<EB, 256>>>();
    vert_kernel<<<(NEDGE + 255) / 256, 256>>>(out);
    face_kernel<<<TB, 256>>>(out);
}